// round 2
// baseline (speedup 1.0000x reference)
#include <cuda_runtime.h>

// APLoss: loss-only AP loss over N logits with FG=256 foreground entries.
//
// Math:  for sorted fg values f_0 <= ... <= f_255:
//   a_i = 0.5 + sum_j clip((f_j - f_i)/2 + 0.5, 0, 1)            (256x256, trivial)
//   b_i = sum_{bg l} clip((l - f_i)/2 + 0.5, 0, 1)
//       = CntGE(f_i+1) + 0.5*(SumGE(f_i-1)-SumGE(f_i+1))
//         + (0.5 - 0.5*f_i)*(CntGE(f_i-1)-CntGE(f_i+1))
//   cur_i = a_i/(a_i+b_i);  prec_i = running max over ascending i
//   loss = 1 - sum(prec)/fg_num
//
// CntGE/SumGE evaluated at the 512 merged thresholds via a 513-bucket
// histogram (one binary search + <=2 shared atomics per element).

#define FGMAX 256
#define NT    512   // thresholds
#define NB    513   // buckets (0 = below all thresholds, NT = above all)

__device__ int    g_fg_cnt;
__device__ float  g_fg_raw[FGMAX];
__device__ float  g_sortedF[FGMAX];
__device__ float  g_T[NT];
__device__ int    g_posLow[FGMAX];   // index in T of (f_i - 1)
__device__ int    g_posHigh[FGMAX];  // index in T of (f_i + 1)
__device__ int    g_cnt[NB];
__device__ double g_sum[NB];

// ---------------------------------------------------------------- init
__global__ void k_init() {
    int i = threadIdx.x;
    if (i == 0) g_fg_cnt = 0;
    if (i < NB) { g_cnt[i] = 0; g_sum[i] = 0.0; }
}

// ---------------------------------------------------------------- extract fg
__global__ void k_extract(const float* __restrict__ logits,
                          const int* __restrict__ targets, int n) {
    int stride = gridDim.x * blockDim.x;
    for (int i = blockIdx.x * blockDim.x + threadIdx.x; i < n; i += stride) {
        if (targets[i] == 1) {
            int p = atomicAdd(&g_fg_cnt, 1);
            if (p < FGMAX) g_fg_raw[p] = logits[i];
        }
    }
}

// ---------------------------------------------------------------- sort fg + build thresholds
__global__ void k_sort() {
    __shared__ float raw[FGMAX];
    __shared__ float sf[FGMAX];
    int t = threadIdx.x;
    if (t < FGMAX) raw[t] = g_fg_raw[t];
    __syncthreads();
    if (t < FGMAX) {
        float v = raw[t];
        int r = 0;
        #pragma unroll 8
        for (int j = 0; j < FGMAX; ++j) {
            float u = raw[j];
            r += (u < v) || (u == v && j < t);
        }
        sf[r] = v;
        g_sortedF[r] = v;
    }
    __syncthreads();
    // merge {f_i - 1} and {f_i + 1} into sorted T[512] (rank with index tiebreak)
    float v = (t < FGMAX) ? (sf[t] - 1.0f) : (sf[t - FGMAX] + 1.0f);
    int r = 0;
    #pragma unroll 8
    for (int j = 0; j < NT; ++j) {
        float u = (j < FGMAX) ? (sf[j] - 1.0f) : (sf[j - FGMAX] + 1.0f);
        r += (u < v) || (u == v && j < t);
    }
    g_T[r] = v;
    if (t < FGMAX) g_posLow[t] = r;
    else           g_posHigh[t - FGMAX] = r;
}

// ---------------------------------------------------------------- histogram (hot kernel)
__device__ __forceinline__ void hist_one(float l, float t0,
                                         const float* sT, int* sCnt, float* sSum) {
    if (l < t0) return;                 // bucket 0: contributes nothing
    int p = 0;
    #pragma unroll
    for (int s = 512; s > 0; s >>= 1) { // p = #{T <= l} in [1, 512]
        int np = p + s;
        if (np <= NT && sT[np - 1] <= l) p = np;
    }
    atomicAdd(&sCnt[p], 1);
    if (p < NT) atomicAdd(&sSum[p], l); // overflow bucket needs count only
}

__global__ void k_hist(const float* __restrict__ logits, int n) {
    __shared__ float sT[NT];
    __shared__ int   sCnt[NB];
    __shared__ float sSum[NB];
    for (int i = threadIdx.x; i < NB; i += blockDim.x) { sCnt[i] = 0; sSum[i] = 0.0f; }
    for (int i = threadIdx.x; i < NT; i += blockDim.x) sT[i] = g_T[i];
    __syncthreads();
    float t0 = sT[0];

    int tid = blockIdx.x * blockDim.x + threadIdx.x;
    int stride = gridDim.x * blockDim.x;
    int n4 = n >> 2;
    const float4* l4 = (const float4*)logits;
    for (int i = tid; i < n4; i += stride) {
        float4 v = l4[i];
        hist_one(v.x, t0, sT, sCnt, sSum);
        hist_one(v.y, t0, sT, sCnt, sSum);
        hist_one(v.z, t0, sT, sCnt, sSum);
        hist_one(v.w, t0, sT, sCnt, sSum);
    }
    for (int i = (n4 << 2) + tid; i < n; i += stride)
        hist_one(logits[i], t0, sT, sCnt, sSum);

    __syncthreads();
    for (int i = threadIdx.x; i < NB; i += blockDim.x) {
        int c = sCnt[i];
        if (c) atomicAdd(&g_cnt[i], c);
        float s = sSum[i];
        if (s != 0.0f) atomicAdd(&g_sum[i], (double)s);
    }
}

// ---------------------------------------------------------------- epilogue
__global__ void k_final(const int* __restrict__ fg_num_ptr, float* __restrict__ out) {
    __shared__ float  sT[NT];
    __shared__ float  sf[FGMAX];
    __shared__ int    cntS[NB];
    __shared__ double sumS[NB];
    __shared__ double cntGE[NT];
    __shared__ double sumGE[NT];
    __shared__ float  scur[FGMAX];
    int t = threadIdx.x;

    for (int i = t; i < NT; i += blockDim.x) sT[i] = g_T[i];
    for (int i = t; i < NB; i += blockDim.x) { cntS[i] = g_cnt[i]; sumS[i] = g_sum[i]; }
    if (t < FGMAX) sf[t] = g_sortedF[t];
    __syncthreads();

    // remove fg elements from the histogram (they were binned in k_hist)
    if (t < FGMAX) {
        float f = sf[t];
        if (f >= sT[0]) {
            int p = 0;
            #pragma unroll
            for (int s = 512; s > 0; s >>= 1) {
                int np = p + s;
                if (np <= NT && sT[np - 1] <= f) p = np;
            }
            atomicAdd(&cntS[p], -1);
            if (p < NT) atomicAdd(&sumS[p], -(double)f);
        }
    }
    __syncthreads();

    if (t == 0) {
        double accS = 0.0, accC = 0.0;
        for (int b = NT; b >= 1; --b) {
            accC += (double)cntS[b];
            accS += sumS[b];
            cntGE[b - 1] = accC;   // CntGE(T[b-1])
            sumGE[b - 1] = accS;   // SumGE(T[b-1])
        }
    }
    __syncthreads();

    if (t < FGMAX) {
        float fi = sf[t];
        float a = 0.5f;
        #pragma unroll 8
        for (int j = 0; j < FGMAX; ++j)
            a += __saturatef((sf[j] - fi) * 0.5f + 0.5f);
        int lp = g_posLow[t], hp = g_posHigh[t];
        double ones = cntGE[hp];
        double wc   = cntGE[lp] - ones;
        double ws   = sumGE[lp] - sumGE[hp];
        double bb   = ones + 0.5 * ws + (0.5 - 0.5 * (double)fi) * wc;
        scur[t] = (float)((double)a / ((double)a + bb));
    }
    __syncthreads();

    if (t == 0) {
        float mp = 0.0f, acc = 0.0f;
        for (int i = 0; i < FGMAX; ++i) {
            mp = fmaxf(mp, scur[i]);
            acc += mp;
        }
        int fgn = *fg_num_ptr;
        if (fgn < 1) fgn = 1;
        out[0] = 1.0f - acc / (float)fgn;
    }
}

// ---------------------------------------------------------------- launch
extern "C" void kernel_launch(void* const* d_in, const int* in_sizes, int n_in,
                              void* d_out, int out_size) {
    const float* logits  = (const float*)d_in[0];
    const int*   targets = (const int*)d_in[1];
    const int*   fg_num  = (const int*)d_in[2];
    float* out = (float*)d_out;
    int n = in_sizes[0];

    k_init<<<1, 1024>>>();
    k_extract<<<1184, 256>>>(logits, targets, n);
    k_sort<<<1, 512>>>();
    k_hist<<<592, 256>>>(logits, n);
    k_final<<<1, 512>>>(fg_num, out);
}

// round 4
// speedup vs baseline: 2.6588x; 2.6588x over previous
#include <cuda_runtime.h>

// APLoss: loss-only AP loss over N logits with FG=256 foreground entries.
//
// b_i over background logits reduces to CDF stats at the 512 merged
// thresholds {f-1} u {f+1}:
//   b_i = CntGE(f_i+1) + 0.5*(SumGE(f_i-1)-SumGE(f_i+1))
//         + (0.5-0.5*f_i)*(CntGE(f_i-1)-CntGE(f_i+1))
// computed via a 513-bucket histogram.
//
// SAFETY INVARIANT: no data-dependent while loops anywhere on the device.
// The hot-kernel bucket search is either a fixed 5-step windowed binary
// search (validity of the 32-wide window is PROVEN in k_sort and gated by
// g_fast) or the fixed 10-step full binary search fallback.

#define FGMAX 256
#define NT    512
#define NB    513
#define LUTN  4096

__device__ int            g_fg_cnt;        // zero-init; reset at end of k_final
__device__ float          g_fg_raw[FGMAX];
__device__ float          g_sortedF[FGMAX];
__device__ float          g_T[NT];
__device__ int            g_posLow[FGMAX];
__device__ int            g_posHigh[FGMAX];
__device__ int            g_cnt[NB];       // zero-init; reset at end of k_final
__device__ double         g_sum[NB];       // zero-init; reset at end of k_final
__device__ unsigned short g_lut[LUTN];
__device__ float          g_tmin, g_scale;
__device__ int            g_fast;          // 1 => windowed search valid

// ---------------------------------------------------------------- extract fg
__global__ void k_extract(const float* __restrict__ logits,
                          const int* __restrict__ targets, int n) {
    int stride = gridDim.x * blockDim.x;
    int tid = blockIdx.x * blockDim.x + threadIdx.x;
    int n4 = n >> 2;
    const int4* t4 = (const int4*)targets;
    for (int i = tid; i < n4; i += stride) {
        int4 v = t4[i];
        if (v.x | v.y | v.z | v.w) {
            int base = i << 2;
            if (v.x) { int p = atomicAdd(&g_fg_cnt, 1); if (p < FGMAX) g_fg_raw[p] = logits[base]; }
            if (v.y) { int p = atomicAdd(&g_fg_cnt, 1); if (p < FGMAX) g_fg_raw[p] = logits[base + 1]; }
            if (v.z) { int p = atomicAdd(&g_fg_cnt, 1); if (p < FGMAX) g_fg_raw[p] = logits[base + 2]; }
            if (v.w) { int p = atomicAdd(&g_fg_cnt, 1); if (p < FGMAX) g_fg_raw[p] = logits[base + 3]; }
        }
    }
    for (int i = (n4 << 2) + tid; i < n; i += stride)
        if (targets[i] == 1) { int p = atomicAdd(&g_fg_cnt, 1); if (p < FGMAX) g_fg_raw[p] = logits[i]; }
}

// ------------------------------- sort fg + merge thresholds + LUT + validate
__global__ void k_sort() {
    __shared__ float raw[FGMAX];
    __shared__ float sf[FGMAX];
    __shared__ float sT[NT];
    __shared__ unsigned short lutS[LUTN];
    __shared__ int smax;
    int t = threadIdx.x;  // 512 threads
    if (t == 0) smax = 0;

    if (t < FGMAX) raw[t] = g_fg_raw[t];
    __syncthreads();
    if (t < FGMAX) {
        float v = raw[t];
        int r = 0;
        #pragma unroll 8
        for (int j = 0; j < FGMAX; ++j) {          // fixed 256 iterations
            float u = raw[j];
            r += (u < v) || (u == v && j < t);
        }
        sf[r] = v;
        g_sortedF[r] = v;
    }
    __syncthreads();

    // merge {sf-1} and {sf+1} (each sorted) by fixed 8-step binary search.
    if (t < FGMAX) {
        float v = sf[t] - 1.0f;
        int lo = 0;                                 // #{high < v}, high sorted
        #pragma unroll
        for (int s = 256; s > 0; s >>= 1) {         // fixed 9 steps
            int nl = lo + s;
            if (nl <= FGMAX && sf[nl - 1] + 1.0f < v) lo = nl;
        }
        int pos = t + lo;
        sT[pos] = v; g_T[pos] = v; g_posLow[t] = pos;
    } else {
        int i = t - FGMAX;
        float v = sf[i] + 1.0f;
        int lo = 0;                                 // #{low <= v}
        #pragma unroll
        for (int s = 256; s > 0; s >>= 1) {
            int nl = lo + s;
            if (nl <= FGMAX && sf[nl - 1] - 1.0f <= v) lo = nl;
        }
        int pos = i + lo;
        sT[pos] = v; g_T[pos] = v; g_posHigh[i] = pos;
    }
    __syncthreads();

    float tmin = sT[0], tmax = sT[NT - 1];
    float range = tmax - tmin;
    float cellw = range * (1.0f / (float)LUTN);
    if (t == 0) {
        g_tmin = tmin;
        g_scale = (range > 0.0f) ? ((float)LUTN / range) : 0.0f;
    }
    // LUT: lut[c] = #{T <= cellLo_c}, via fixed 10-step search
    for (int c = t; c < LUTN; c += 512) {
        float cellLo = tmin + (float)c * cellw;
        int p = 0;
        #pragma unroll
        for (int s = 512; s > 0; s >>= 1) {
            int np = p + s;
            if (np <= NT && sT[np - 1] <= cellLo) p = np;
        }
        lutS[c] = (unsigned short)p;
        g_lut[c] = (unsigned short)p;
    }
    __syncthreads();
    // validate the 32-wide search window: for every cell c, any element
    // mapping to c has true bucket within [p0(c), p0(c)+31], where
    // p0(c)=lut[c-1] (lut[0]=0 for c=0) and the upper bound is lut[c+2]/NT.
    for (int c = t; c < LUTN; c += 512) {
        int p0 = (c > 0) ? (int)lutS[c - 1] : 0;
        int U  = (c + 2 < LUTN) ? (int)lutS[c + 2] : NT;
        atomicMax(&smax, U - p0);
    }
    __syncthreads();
    if (t == 0) g_fast = (smax <= 31) ? 1 : 0;
}

// ---------------------------------------------------------------- histogram
__device__ __forceinline__ int bucket_fast(float l, float tmin, float scale,
                                           const float* sT,
                                           const unsigned short* sLut) {
    float x = (l - tmin) * scale;
    int c = max(0, min(LUTN - 1, (int)x));
    int p = (c > 0) ? (int)sLut[c - 1] : 0;
    #pragma unroll
    for (int s = 16; s > 0; s >>= 1) {              // fixed 5 steps, window 32
        int np = p + s;
        if (np <= NT && sT[np - 1] <= l) p = np;
    }
    return p;
}

__device__ __forceinline__ int bucket_full(float l, const float* sT) {
    int p = 0;
    #pragma unroll
    for (int s = 512; s > 0; s >>= 1) {             // fixed 10 steps
        int np = p + s;
        if (np <= NT && sT[np - 1] <= l) p = np;
    }
    return p;
}

__device__ __forceinline__ void hist_commit(int p, float l, int* sCnt, float* sSum) {
    if (p > 0) {
        atomicAdd(&sCnt[p], 1);
        if (p < NT) atomicAdd(&sSum[p], l);
    }
}

__global__ void k_hist(const float* __restrict__ logits, int n) {
    __shared__ float sT[NT];
    __shared__ unsigned short sLut[LUTN];
    __shared__ int   sCnt[NB];
    __shared__ float sSum[NB];
    int td = threadIdx.x;
    for (int i = td; i < NB; i += blockDim.x) { sCnt[i] = 0; sSum[i] = 0.0f; }
    for (int i = td; i < NT; i += blockDim.x) sT[i] = g_T[i];
    for (int i = td; i < LUTN; i += blockDim.x) sLut[i] = g_lut[i];
    __syncthreads();
    float tmin = g_tmin, scale = g_scale;
    int fast = g_fast;                               // uniform branch

    int tid = blockIdx.x * blockDim.x + td;
    int stride = gridDim.x * blockDim.x;
    int n4 = n >> 2;
    const float4* l4 = (const float4*)logits;
    if (fast) {
        for (int i = tid; i < n4; i += stride) {
            float4 v = l4[i];
            hist_commit(bucket_fast(v.x, tmin, scale, sT, sLut), v.x, sCnt, sSum);
            hist_commit(bucket_fast(v.y, tmin, scale, sT, sLut), v.y, sCnt, sSum);
            hist_commit(bucket_fast(v.z, tmin, scale, sT, sLut), v.z, sCnt, sSum);
            hist_commit(bucket_fast(v.w, tmin, scale, sT, sLut), v.w, sCnt, sSum);
        }
        for (int i = (n4 << 2) + tid; i < n; i += stride) {
            float l = logits[i];
            hist_commit(bucket_fast(l, tmin, scale, sT, sLut), l, sCnt, sSum);
        }
    } else {
        for (int i = tid; i < n4; i += stride) {
            float4 v = l4[i];
            hist_commit(bucket_full(v.x, sT), v.x, sCnt, sSum);
            hist_commit(bucket_full(v.y, sT), v.y, sCnt, sSum);
            hist_commit(bucket_full(v.z, sT), v.z, sCnt, sSum);
            hist_commit(bucket_full(v.w, sT), v.w, sCnt, sSum);
        }
        for (int i = (n4 << 2) + tid; i < n; i += stride) {
            float l = logits[i];
            hist_commit(bucket_full(l, sT), l, sCnt, sSum);
        }
    }

    __syncthreads();
    for (int i = td; i < NB; i += blockDim.x) {
        int c = sCnt[i];
        if (c) atomicAdd(&g_cnt[i], c);
        float s = sSum[i];
        if (s != 0.0f) atomicAdd(&g_sum[i], (double)s);
    }
}

// ---------------------------------------------------------------- epilogue
__global__ void k_final(const int* __restrict__ fg_num_ptr, float* __restrict__ out) {
    __shared__ float  sT[NT];
    __shared__ float  sf[FGMAX];
    __shared__ int    cntS[NB];
    __shared__ double sumS[NB];
    __shared__ double xc[NT];     // xc[i] = CntGE(T[i])
    __shared__ double xs[NT];     // xs[i] = SumGE(T[i])
    __shared__ float  cur[FGMAX];
    int t = threadIdx.x;  // 512 threads

    for (int i = t; i < NT; i += 512) sT[i] = g_T[i];
    for (int i = t; i < NB; i += 512) { cntS[i] = g_cnt[i]; sumS[i] = g_sum[i]; }
    if (t < FGMAX) sf[t] = g_sortedF[t];
    __syncthreads();

    // remove fg elements from the histogram (they were binned in k_hist)
    if (t < FGMAX) {
        float f = sf[t];
        int p = 0;
        #pragma unroll
        for (int s = 512; s > 0; s >>= 1) {
            int np = p + s;
            if (np <= NT && sT[np - 1] <= f) p = np;
        }
        if (p > 0) {
            atomicAdd(&cntS[p], -1);
            if (p < NT) atomicAdd(&sumS[p], -(double)f);
        }
    }
    __syncthreads();

    // parallel suffix scan over buckets 1..512
    xc[t] = (double)cntS[t + 1];
    xs[t] = sumS[t + 1];
    __syncthreads();
    #pragma unroll
    for (int off = 1; off < NT; off <<= 1) {
        double ac = 0.0, as = 0.0;
        if (t + off < NT) { ac = xc[t + off]; as = xs[t + off]; }
        __syncthreads();
        xc[t] += ac; xs[t] += as;
        __syncthreads();
    }

    if (t < FGMAX) {
        float fi = sf[t];
        float a = 0.5f;
        #pragma unroll 8
        for (int j = 0; j < FGMAX; ++j)
            a += __saturatef((sf[j] - fi) * 0.5f + 0.5f);
        int lp = g_posLow[t], hp = g_posHigh[t];
        double ones = xc[hp];
        double wc   = xc[lp] - ones;
        double ws   = xs[lp] - xs[hp];
        double bb   = ones + 0.5 * ws + (0.5 - 0.5 * (double)fi) * wc;
        cur[t] = (float)((double)a / ((double)a + bb));
    }
    __syncthreads();

    // prefix-max scan (running precision), then tree-sum
    #pragma unroll
    for (int off = 1; off < FGMAX; off <<= 1) {
        float m = -1.0f;
        if (t < FGMAX && t >= off) m = cur[t - off];
        __syncthreads();
        if (t < FGMAX) cur[t] = fmaxf(cur[t], m);
        __syncthreads();
    }
    #pragma unroll
    for (int off = FGMAX >> 1; off > 0; off >>= 1) {
        if (t < off) cur[t] += cur[t + off];
        __syncthreads();
    }
    if (t == 0) {
        int fgn = *fg_num_ptr;
        if (fgn < 1) fgn = 1;
        out[0] = 1.0f - cur[0] / (float)fgn;
    }

    // reset global accumulators for the next (deterministic) replay
    __syncthreads();
    for (int i = t; i < NB; i += 512) { g_cnt[i] = 0; g_sum[i] = 0.0; }
    if (t == 0) g_fg_cnt = 0;
}

// ---------------------------------------------------------------- launch
extern "C" void kernel_launch(void* const* d_in, const int* in_sizes, int n_in,
                              void* d_out, int out_size) {
    const float* logits  = (const float*)d_in[0];
    const int*   targets = (const int*)d_in[1];
    const int*   fg_num  = (const int*)d_in[2];
    float* out = (float*)d_out;
    int n = in_sizes[0];

    k_extract<<<592, 256>>>(logits, targets, n);
    k_sort<<<1, 512>>>();
    k_hist<<<592, 256>>>(logits, n);
    k_final<<<1, 512>>>(fg_num, out);
}